// round 9
// baseline (speedup 1.0000x reference)
#include <cuda_runtime.h>
#include <cstdint>

#define H_IMG 64
#define W_IMG 64
#define CH    128
#define HD    32
#define HEADS 4
#define KS    3
#define DIL   2
#define KK    9
#define PLANE 4096

#define TXD 16
#define TYD 16
#define NTHREADS (TXD*TYD)     // 256
#define TW 32                  // tile width (pixels), 2 per thread in x
#define TH 16                  // tile height

#define CPC 4                  // channels per stage
#define NST_K 8                // k stages
#define NST   16               // total stages (k then v)
#define SH 20                  // TH + halo 2 each side
#define SWP 40                 // padded cols: gx in [tileX-4, tileX+36)
#define SEGS 10                // float4 segments per row
#define CELLS (CPC*SH*SEGS)    // 800
#define STAGE_FLOATS (CPC*SH*SWP)   // 3200 (12.8 KB)
#define RING 3

__device__ __forceinline__ uint32_t s2u(const void* p) {
    return (uint32_t)__cvta_generic_to_shared(p);
}

// issue one stage's 800 16B cp.asyncs (zfill out-of-image); commits a group
__device__ __forceinline__ void issue_stage(const float* __restrict__ src,
                                            float* __restrict__ dst,
                                            int tid, int tileX, int tileY)
{
#pragma unroll
    for (int ii = 0; ii < 4; ii++) {
        const int i = tid + ii * NTHREADS;
        if (i < CELLS) {
            const int ch  = i / (SH * SEGS);
            const int rem = i - ch * (SH * SEGS);
            const int row = rem / SEGS;
            const int seg = rem - row * SEGS;
            const int gy  = tileY - 2 + row;
            const int gx  = tileX - 4 + seg * 4;
            const bool inb = (gy >= 0) & (gy < H_IMG) & (gx >= 0) & (gx < W_IMG);
            const float* gp = inb ? (src + ch * PLANE + gy * W_IMG + gx) : src;
            const int sz = inb ? 16 : 0;
            const uint32_t sa = s2u(dst + ch * (SH * SWP) + row * SWP + seg * 4);
            asm volatile("cp.async.cg.shared.global [%0], [%1], 16, %2;\n"
                         :: "r"(sa), "l"(gp), "r"(sz) : "memory");
        }
    }
    asm volatile("cp.async.commit_group;\n" ::: "memory");
}

#define CP_COMMIT_EMPTY() asm volatile("cp.async.commit_group;\n" ::: "memory")
#define CP_WAIT1() asm volatile("cp.async.wait_group 1;\n" ::: "memory")

__global__ __launch_bounds__(NTHREADS, 5)
void dilate_attn_kernel(const float* __restrict__ q,
                        const float* __restrict__ k,
                        const float* __restrict__ v,
                        float* __restrict__ out)
{
    __shared__ __align__(16) float ring[RING][STAGE_FLOATS];   // 38.4 KB

    const int tx  = threadIdx.x;              // 0..15 -> pixel pair 2tx, 2tx+1
    const int ty  = threadIdx.y;              // 0..15
    const int tid = ty * TXD + tx;

    const int tilesX = W_IMG / TW;            // 2
    const int tileX = (blockIdx.x % tilesX) * TW;
    const int tileY = (blockIdx.x / tilesX) * TH;
    const int head  = blockIdx.y;
    const int b     = blockIdx.z;

    const int x0   = tileX + 2 * tx;          // pixel A (B = A+1)
    const int y    = tileY + ty;
    const int pixA = y * W_IMG + x0;

    const float scale = 0.1767766952966369f;  // 32^-0.5

    const size_t base = ((size_t)b * CH + head * HD) * PLANE;
    const float* kb = k + base;
    const float* vb = v + base;
    const float* qb = q + base + pixA;        // 8B aligned (pixA even)

    // prologue: issue k stages 0,1
    issue_stage(kb,             ring[0], tid, tileX, tileY);
    issue_stage(kb + 4 * PLANE, ring[1], tid, tileX, tileY);

    float lA[KK], lB[KK];
#pragma unroll
    for (int i = 0; i < KK; i++) { lA[i] = 0.f; lB[i] = 0.f; }

    // ================= q.k stages 0..7 =================
#pragma unroll
    for (int s = 0; s < NST_K; s++) {
        CP_WAIT1();
        __syncthreads();

        // q for this stage's 4 channels, both pixels (LDG.64 each)
        float2 qv[CPC];
#pragma unroll
        for (int c = 0; c < CPC; c++)
            qv[c] = *reinterpret_cast<const float2*>(qb + (size_t)(s * CPC + c) * PLANE);

        // issue stage s+2 (k stages 2..7, then v stages 0,1)
        {
            const int sn = s + 2;
            const float* src = (sn < NST_K) ? (kb + sn * CPC * PLANE)
                                            : (vb + (sn - NST_K) * CPC * PLANE);
            issue_stage(src, ring[sn % RING], tid, tileX, tileY);
        }

        const float* tb = ring[s % RING];
#pragma unroll
        for (int c = 0; c < CPC; c++) {
            // pair tap base: col (2tx+2) = taps (kj=0) for A(.x)/B(.y)
            const float* tc = tb + c * (SH * SWP) + ty * SWP + 2 * tx + 2;
            const float qA = qv[c].x, qB = qv[c].y;
#pragma unroll
            for (int ki = 0; ki < KS; ki++)
#pragma unroll
                for (int kj = 0; kj < KS; kj++) {
                    const float2 t = *reinterpret_cast<const float2*>(
                        tc + (2 * ki) * SWP + 2 * kj);
                    const int ti = ki * KS + kj;
                    lA[ti] = fmaf(qA, t.x, lA[ti]);
                    lB[ti] = fmaf(qB, t.y, lB[ti]);
                }
        }
    }

    // ================= softmax over 9 taps (both pixels) =================
    {
        float mA = -1e30f, mB = -1e30f;
#pragma unroll
        for (int i = 0; i < KK; i++) {
            lA[i] *= scale; lB[i] *= scale;
            mA = fmaxf(mA, lA[i]); mB = fmaxf(mB, lB[i]);
        }
        float sA = 0.f, sB = 0.f;
#pragma unroll
        for (int i = 0; i < KK; i++) {
            lA[i] = __expf(lA[i] - mA); sA += lA[i];
            lB[i] = __expf(lB[i] - mB); sB += lB[i];
        }
        const float iA = 1.f / sA, iB = 1.f / sB;
#pragma unroll
        for (int i = 0; i < KK; i++) { lA[i] *= iA; lB[i] *= iB; }  // now weights
    }

    // ================= a.v stages 8..15 =================
    float* opA = out + ((size_t)b * PLANE + pixA) * CH + head * HD;
    float* opB = opA + CH;

#pragma unroll
    for (int s = NST_K; s < NST; s++) {
        CP_WAIT1();
        __syncthreads();

        if (s + 2 < NST)
            issue_stage(vb + (s + 2 - NST_K) * CPC * PLANE,
                        ring[(s + 2) % RING], tid, tileX, tileY);
        else
            CP_COMMIT_EMPTY();   // keep group count ahead so CP_WAIT1 drains stage s

        const float* tb = ring[s % RING];
        float oA[CPC], oB[CPC];
#pragma unroll
        for (int c = 0; c < CPC; c++) {
            const float* tc = tb + c * (SH * SWP) + ty * SWP + 2 * tx + 2;
            float aA = 0.f, aB = 0.f;
#pragma unroll
            for (int ki = 0; ki < KS; ki++)
#pragma unroll
                for (int kj = 0; kj < KS; kj++) {
                    const float2 t = *reinterpret_cast<const float2*>(
                        tc + (2 * ki) * SWP + 2 * kj);
                    const int ti = ki * KS + kj;
                    aA = fmaf(lA[ti], t.x, aA);
                    aB = fmaf(lB[ti], t.y, aB);
                }
            oA[c] = aA; oB[c] = aB;
        }

        const int c0 = (s - NST_K) * CPC;
        *reinterpret_cast<float4*>(opA + c0) = make_float4(oA[0], oA[1], oA[2], oA[3]);
        *reinterpret_cast<float4*>(opB + c0) = make_float4(oB[0], oB[1], oB[2], oB[3]);
    }
}

extern "C" void kernel_launch(void* const* d_in, const int* in_sizes, int n_in,
                              void* d_out, int out_size)
{
    const float* q = (const float*)d_in[0];
    const float* k = (const float*)d_in[1];
    const float* v = (const float*)d_in[2];
    float* out = (float*)d_out;

    dim3 block(TXD, TYD);
    dim3 grid((W_IMG / TW) * (H_IMG / TH), HEADS, 16 /*B*/);
    dilate_attn_kernel<<<grid, block>>>(q, k, v, out);
}

// round 10
// speedup vs baseline: 1.2256x; 1.2256x over previous
#include <cuda_runtime.h>
#include <cstdint>

#define H_IMG 64
#define W_IMG 64
#define CH    128
#define HD    32
#define HEADS 4
#define KS    3
#define DIL   2
#define KK    9
#define PLANE 4096

#define TW 32                  // tile width (pixels)
#define TH 8                   // tile height
#define NTHREADS (TW*TH)       // 256, 1 pixel per thread

#define CPC 4                  // channels per stage
#define NST_K 8                // k stages
#define NST   16               // total stages (k then v)
#define SH (TH + 4)            // 12 rows
#define SWP 40                 // padded cols: gx in [tileX-4, tileX+36)
#define SEGS 10                // float4 segments per row
#define CELLS (CPC*SH*SEGS)    // 480
#define STAGE_FLOATS (CPC*SH*SWP)   // 1920 (7.5 KB)
#define RING 3

__device__ __forceinline__ uint32_t s2u(const void* p) {
    return (uint32_t)__cvta_generic_to_shared(p);
}

// issue one stage's 480 16B cp.asyncs (zfill out-of-image); commits a group
__device__ __forceinline__ void issue_stage(const float* __restrict__ src,
                                            float* __restrict__ dst,
                                            int tid, int tileX, int tileY)
{
#pragma unroll
    for (int ii = 0; ii < 2; ii++) {
        const int i = tid + ii * NTHREADS;
        if (i < CELLS) {
            const int ch  = i / (SH * SEGS);
            const int rem = i - ch * (SH * SEGS);
            const int row = rem / SEGS;
            const int seg = rem - row * SEGS;
            const int gy  = tileY - 2 + row;
            const int gx  = tileX - 4 + seg * 4;
            const bool inb = (gy >= 0) & (gy < H_IMG) & (gx >= 0) & (gx < W_IMG);
            const float* gp = inb ? (src + ch * PLANE + gy * W_IMG + gx) : src;
            const int sz = inb ? 16 : 0;
            const uint32_t sa = s2u(dst + ch * (SH * SWP) + row * SWP + seg * 4);
            asm volatile("cp.async.cg.shared.global [%0], [%1], 16, %2;\n"
                         :: "r"(sa), "l"(gp), "r"(sz) : "memory");
        }
    }
    asm volatile("cp.async.commit_group;\n" ::: "memory");
}

#define CP_COMMIT_EMPTY() asm volatile("cp.async.commit_group;\n" ::: "memory")
#define CP_WAIT1() asm volatile("cp.async.wait_group 1;\n" ::: "memory")

__global__ __launch_bounds__(NTHREADS, 6)
void dilate_attn_kernel(const float* __restrict__ q,
                        const float* __restrict__ k,
                        const float* __restrict__ v,
                        float* __restrict__ out)
{
    __shared__ __align__(16) float ring[RING][STAGE_FLOATS];   // 22.5 KB

    const int tx  = threadIdx.x;              // 0..31
    const int ty  = threadIdx.y;              // 0..7
    const int tid = ty * TW + tx;

    const int tilesX = W_IMG / TW;            // 2
    const int tileX = (blockIdx.x % tilesX) * TW;
    const int tileY = (blockIdx.x / tilesX) * TH;
    const int head  = blockIdx.y;
    const int b     = blockIdx.z;

    const int x   = tileX + tx;
    const int y   = tileY + ty;
    const int pix = y * W_IMG + x;

    const float scale = 0.1767766952966369f;  // 32^-0.5

    const size_t base = ((size_t)b * CH + head * HD) * PLANE;
    const float* kb = k + base;
    const float* vb = v + base;
    const float* qb = q + base + pix;

    // prologue: issue k stages 0,1
    issue_stage(kb,             ring[0], tid, tileX, tileY);
    issue_stage(kb + 4 * PLANE, ring[1], tid, tileX, tileY);

    float qcur[CPC], qnxt[CPC];
#pragma unroll
    for (int c = 0; c < CPC; c++) qcur[c] = __ldg(qb + (size_t)c * PLANE);
#pragma unroll
    for (int c = 0; c < CPC; c++) qnxt[c] = __ldg(qb + (size_t)(CPC + c) * PLANE);

    float logit[KK];
#pragma unroll
    for (int i = 0; i < KK; i++) logit[i] = 0.f;

    // ================= q.k stages 0..7 =================
#pragma unroll
    for (int s = 0; s < NST_K; s++) {
        CP_WAIT1();
        __syncthreads();

        // issue stage s+2 (k stages 2..7, then v stages 0,1)
        {
            const int sn = s + 2;
            const float* src = (sn < NST_K) ? (kb + sn * CPC * PLANE)
                                            : (vb + (sn - NST_K) * CPC * PLANE);
            issue_stage(src, ring[sn % RING], tid, tileX, tileY);
        }

        // compute stage s
        const float* tb = ring[s % RING];
#pragma unroll
        for (int c = 0; c < CPC; c++) {
            const float* tc = tb + c * (SH * SWP) + ty * SWP + tx + 2;
            const float qc = qcur[c];
#pragma unroll
            for (int ki = 0; ki < KS; ki++)
#pragma unroll
                for (int kj = 0; kj < KS; kj++)
                    logit[ki * KS + kj] = fmaf(qc, tc[(2 * ki) * SWP + 2 * kj],
                                               logit[ki * KS + kj]);
        }

        // rotate q prefetch (distance 2)
#pragma unroll
        for (int c = 0; c < CPC; c++) qcur[c] = qnxt[c];
        if (s + 2 < NST_K) {
#pragma unroll
            for (int c = 0; c < CPC; c++)
                qnxt[c] = __ldg(qb + (size_t)((s + 2) * CPC + c) * PLANE);
        }
    }

    // ================= softmax over 9 taps =================
    {
        float m = -1e30f;
#pragma unroll
        for (int i = 0; i < KK; i++) {
            logit[i] *= scale;
            m = fmaxf(m, logit[i]);
        }
        float ssum = 0.f;
#pragma unroll
        for (int i = 0; i < KK; i++) {
            logit[i] = __expf(logit[i] - m);
            ssum += logit[i];
        }
        const float inv = 1.f / ssum;
#pragma unroll
        for (int i = 0; i < KK; i++) logit[i] *= inv;   // logit[] = weights now
    }

    // ================= a.v stages 8..15 =================
    float* op = out + ((size_t)b * PLANE + pix) * CH + head * HD;

#pragma unroll
    for (int s = NST_K; s < NST; s++) {
        CP_WAIT1();
        __syncthreads();

        if (s + 2 < NST)
            issue_stage(vb + (s + 2 - NST_K) * CPC * PLANE,
                        ring[(s + 2) % RING], tid, tileX, tileY);
        else
            CP_COMMIT_EMPTY();   // keep group count ahead so CP_WAIT1 drains stage s

        const float* tb = ring[s % RING];
        float o[CPC];
#pragma unroll
        for (int c = 0; c < CPC; c++) {
            const float* tc = tb + c * (SH * SWP) + ty * SWP + tx + 2;
            float acc = 0.f;
#pragma unroll
            for (int ki = 0; ki < KS; ki++)
#pragma unroll
                for (int kj = 0; kj < KS; kj++)
                    acc = fmaf(logit[ki * KS + kj], tc[(2 * ki) * SWP + 2 * kj], acc);
            o[c] = acc;
        }

        *reinterpret_cast<float4*>(op + (s - NST_K) * CPC) =
            make_float4(o[0], o[1], o[2], o[3]);
    }
}

extern "C" void kernel_launch(void* const* d_in, const int* in_sizes, int n_in,
                              void* d_out, int out_size)
{
    const float* q = (const float*)d_in[0];
    const float* k = (const float*)d_in[1];
    const float* v = (const float*)d_in[2];
    float* out = (float*)d_out;

    dim3 block(TW, TH);
    dim3 grid((W_IMG / TW) * (H_IMG / TH), HEADS, 16 /*B*/);
    dilate_attn_kernel<<<grid, block>>>(q, k, v, out);
}